// round 1
// baseline (speedup 1.0000x reference)
#include <cuda_runtime.h>

#define N_NODES 200000
#define N_VAR   112000
#define N_EDGES 3200000
#define HID     64

// ---- device scratch (static, no allocation) ----
__device__ int    g_deg[N_NODES];
__device__ float  g_dinv[N_NODES];
__device__ float2 g_ab[N_NODES];        // self (a,b) = dinv*(x0,x1)
__device__ float2 g_AB[N_NODES];        // layer-1 scalar scatter accumulators
__device__ float4 g_hs[N_NODES * 16];   // hs = relu(conv1) * dinv, 64 floats/node
__device__ float4 g_agg[N_VAR * 16];    // layer-2 scatter accumulators (var nodes only)
__device__ float  g_Wc[64 * 64];        // W2 @ Wfc
__device__ float  g_bc[64];             // b2 @ Wfc + bfc

// ---- zero accumulators ----
__global__ void k_zero() {
    int i = blockIdx.x * blockDim.x + threadIdx.x;
    if (i < N_VAR * 16) g_agg[i] = make_float4(0.f, 0.f, 0.f, 0.f);
    if (i < N_NODES) { g_AB[i] = make_float2(0.f, 0.f); g_deg[i] = 0; }
}

// ---- precompute Wc = W2 @ Wfc, bc = b2 @ Wfc + bfc ----
__global__ void k_prep(const float* __restrict__ W2, const float* __restrict__ b2,
                       const float* __restrict__ Wfc, const float* __restrict__ bfc) {
    int id = blockIdx.x * 256 + threadIdx.x;   // 0..4095
    int i = id >> 6, j = id & 63;
    float s = 0.f;
    #pragma unroll 8
    for (int k = 0; k < 64; k++) s = fmaf(W2[i * 64 + k], Wfc[k * 64 + j], s);
    g_Wc[id] = s;
    if (id < 64) {
        float sb = bfc[id];
        #pragma unroll 8
        for (int k = 0; k < 64; k++) sb = fmaf(b2[k], Wfc[k * 64 + id], sb);
        g_bc[id] = sb;
    }
}

// ---- in-degree over dst ----
__global__ void k_deg(const int* __restrict__ dst) {
    int e = blockIdx.x * blockDim.x + threadIdx.x;
    if (e < N_EDGES) atomicAdd(&g_deg[dst[e]], 1);
}

// ---- per-node: dinv and self (a,b) ----
__global__ void k_node1(const float* __restrict__ x) {
    int i = blockIdx.x * blockDim.x + threadIdx.x;
    if (i >= N_NODES) return;
    float d = rsqrtf((float)g_deg[i] + 1.0f);
    g_dinv[i] = d;
    g_ab[i] = make_float2(d * x[2 * i], d * x[2 * i + 1]);
}

// ---- layer-1 edge pass: scalar (a,b) scatter ----
__global__ void k_edge1(const int* __restrict__ src, const int* __restrict__ dst) {
    int e = blockIdx.x * blockDim.x + threadIdx.x;
    if (e >= N_EDGES) return;
    float2 ab = g_ab[src[e]];
    float2* p = &g_AB[dst[e]];
    asm volatile("red.global.add.v2.f32 [%0], {%1, %2};"
                 :: "l"(p), "f"(ab.x), "f"(ab.y) : "memory");
}

// ---- per-(node,feature): hs = relu(conv1)*dinv ----
__global__ void k_hs(const float* __restrict__ W1, const float* __restrict__ b1) {
    int tid = blockIdx.x * blockDim.x + threadIdx.x;
    if (tid >= N_NODES * 64) return;
    int i = tid >> 6, f = tid & 63;
    float d  = g_dinv[i];
    float2 AB = g_AB[i];
    float2 ab = g_ab[i];
    float s0 = d * (AB.x + ab.x);
    float s1 = d * (AB.y + ab.y);
    float h  = fmaxf(fmaf(s0, W1[f], fmaf(s1, W1[64 + f], b1[f])), 0.f);
    ((float*)g_hs)[tid] = h * d;
}

// ---- layer-2 edge pass: 16 threads/edge, float4 gather + vec4 red scatter ----
__global__ void k_edge2(const int* __restrict__ src, const int* __restrict__ dst) {
    int tid = blockIdx.x * blockDim.x + threadIdx.x;   // < 51.2M, fits int
    int e = tid >> 4;
    if (e >= N_EDGES) return;
    int t = dst[e];
    if (t >= N_VAR) return;          // constraint-node outputs are discarded
    int lane = tid & 15;
    float4 v = g_hs[src[e] * 16 + lane];
    float4* p = &g_agg[t * 16 + lane];
    asm volatile("red.global.add.v4.f32 [%0], {%1, %2, %3, %4};"
                 :: "l"(p), "f"(v.x), "f"(v.y), "f"(v.z), "f"(v.w) : "memory");
}

// ---- final fused: v = dinv*(agg + hs); out = round(relu(v @ Wc + bc)) ----
__global__ void k_out(float* __restrict__ out) {
    __shared__ __align__(16) float wsh[64 * 64];
    __shared__ float vsh[64 * 65];     // padded rows to kill bank conflicts
    __shared__ float bcs[64];
    int tid = threadIdx.x;
    int nb = blockIdx.x * 64;

    #pragma unroll
    for (int t = 0; t < 16; t++) wsh[tid + t * 256] = g_Wc[tid + t * 256];
    if (tid < 64) bcs[tid] = g_bc[tid];

    const float* agg = (const float*)g_agg;
    const float* hs  = (const float*)g_hs;
    #pragma unroll
    for (int t = 0; t < 16; t++) {
        int id = tid + t * 256;
        int r = id >> 6, k = id & 63;
        int node = nb + r;
        float d = g_dinv[node];
        vsh[r * 65 + k] = d * (agg[node * 64 + k] + hs[node * 64 + k]);
    }
    __syncthreads();

    int tx = tid & 15, ty = tid >> 4;   // 16x16 threads, each 4x4 outputs
    float acc[4][4];
    #pragma unroll
    for (int i = 0; i < 4; i++)
        #pragma unroll
        for (int j = 0; j < 4; j++) acc[i][j] = 0.f;

    #pragma unroll
    for (int k = 0; k < 64; k++) {
        float4 b = *(const float4*)&wsh[k * 64 + tx * 4];
        float a0 = vsh[(ty * 4 + 0) * 65 + k];
        float a1 = vsh[(ty * 4 + 1) * 65 + k];
        float a2 = vsh[(ty * 4 + 2) * 65 + k];
        float a3 = vsh[(ty * 4 + 3) * 65 + k];
        acc[0][0] = fmaf(a0, b.x, acc[0][0]); acc[0][1] = fmaf(a0, b.y, acc[0][1]);
        acc[0][2] = fmaf(a0, b.z, acc[0][2]); acc[0][3] = fmaf(a0, b.w, acc[0][3]);
        acc[1][0] = fmaf(a1, b.x, acc[1][0]); acc[1][1] = fmaf(a1, b.y, acc[1][1]);
        acc[1][2] = fmaf(a1, b.z, acc[1][2]); acc[1][3] = fmaf(a1, b.w, acc[1][3]);
        acc[2][0] = fmaf(a2, b.x, acc[2][0]); acc[2][1] = fmaf(a2, b.y, acc[2][1]);
        acc[2][2] = fmaf(a2, b.z, acc[2][2]); acc[2][3] = fmaf(a2, b.w, acc[2][3]);
        acc[3][0] = fmaf(a3, b.x, acc[3][0]); acc[3][1] = fmaf(a3, b.y, acc[3][1]);
        acc[3][2] = fmaf(a3, b.z, acc[3][2]); acc[3][3] = fmaf(a3, b.w, acc[3][3]);
    }

    float bc0 = bcs[tx * 4 + 0], bc1 = bcs[tx * 4 + 1];
    float bc2 = bcs[tx * 4 + 2], bc3 = bcs[tx * 4 + 3];
    #pragma unroll
    for (int i = 0; i < 4; i++) {
        int node = nb + ty * 4 + i;
        float4 o;
        o.x = rintf(fmaxf(acc[i][0] + bc0, 0.f));
        o.y = rintf(fmaxf(acc[i][1] + bc1, 0.f));
        o.z = rintf(fmaxf(acc[i][2] + bc2, 0.f));
        o.w = rintf(fmaxf(acc[i][3] + bc3, 0.f));
        *(float4*)&out[node * 64 + tx * 4] = o;
    }
}

extern "C" void kernel_launch(void* const* d_in, const int* in_sizes, int n_in,
                              void* d_out, int out_size) {
    const float* x   = (const float*)d_in[0];
    const int*   ei  = (const int*)d_in[1];
    const float* W1  = (const float*)d_in[2];
    const float* b1  = (const float*)d_in[3];
    const float* W2  = (const float*)d_in[4];
    const float* b2  = (const float*)d_in[5];
    const float* Wfc = (const float*)d_in[6];
    const float* bfc = (const float*)d_in[7];
    float* out = (float*)d_out;
    const int* src = ei;
    const int* dst = ei + N_EDGES;

    k_zero <<<(N_VAR * 16 + 255) / 256, 256>>>();
    k_prep <<<16, 256>>>(W2, b2, Wfc, bfc);
    k_deg  <<<(N_EDGES + 255) / 256, 256>>>(dst);
    k_node1<<<(N_NODES + 255) / 256, 256>>>(x);
    k_edge1<<<(N_EDGES + 255) / 256, 256>>>(src, dst);
    k_hs   <<<(N_NODES * 64 + 255) / 256, 256>>>(W1, b1);
    k_edge2<<<(N_EDGES * 16) / 256, 256>>>(src, dst);
    k_out  <<<N_VAR / 64, 256>>>(out);
}

// round 3
// speedup vs baseline: 1.6102x; 1.6102x over previous
#include <cuda_runtime.h>

#define N_NODES 200000
#define N_VAR   112000
#define N_EDGES 3200000

// ---- device scratch (static, no allocation) ----
__device__ int    g_deg[N_NODES];
__device__ int    g_rowstart[N_NODES];
__device__ int    g_pos[N_NODES];
__device__ int    g_srcs[N_EDGES];
__device__ float  g_dinv[N_NODES];
__device__ float2 g_ab[N_NODES];        // self (a,b) = dinv*(x0,x1)
__device__ float4 g_hs[N_NODES * 16];   // hs = relu(conv1) * dinv, 64 floats/node
__device__ float  g_Wc[64 * 64];        // W2 @ Wfc
__device__ float  g_bc[64];             // b2 @ Wfc + bfc
__device__ int    g_total;

// ---- zero degree counters ----
__global__ void k_zero() {
    int i = blockIdx.x * blockDim.x + threadIdx.x;
    if (i < N_NODES) g_deg[i] = 0;
    if (i == 0) g_total = 0;
}

// ---- precompute Wc = W2 @ Wfc, bc = b2 @ Wfc + bfc ----
__global__ void k_prep(const float* __restrict__ W2, const float* __restrict__ b2,
                       const float* __restrict__ Wfc, const float* __restrict__ bfc) {
    int id = blockIdx.x * 256 + threadIdx.x;   // 0..4095
    int i = id >> 6, j = id & 63;
    float s = 0.f;
    #pragma unroll 8
    for (int k = 0; k < 64; k++) s = fmaf(W2[i * 64 + k], Wfc[k * 64 + j], s);
    g_Wc[id] = s;
    if (id < 64) {
        float sb = bfc[id];
        #pragma unroll 8
        for (int k = 0; k < 64; k++) sb = fmaf(b2[k], Wfc[k * 64 + id], sb);
        g_bc[id] = sb;
    }
}

// ---- in-degree over dst ----
__global__ void k_deg(const int* __restrict__ dst) {
    int e = blockIdx.x * blockDim.x + threadIdx.x;
    if (e < N_EDGES) atomicAdd(&g_deg[dst[e]], 1);
}

// ---- per-node: dinv and self (a,b) ----
__global__ void k_node1(const float* __restrict__ x) {
    int i = blockIdx.x * blockDim.x + threadIdx.x;
    if (i >= N_NODES) return;
    float d = rsqrtf((float)g_deg[i] + 1.0f);
    g_dinv[i] = d;
    g_ab[i] = make_float2(d * x[2 * i], d * x[2 * i + 1]);
}

// ---- allocate contiguous CSR range per node ----
__global__ void k_alloc() {
    int i = blockIdx.x * blockDim.x + threadIdx.x;
    if (i >= N_NODES) return;
    int d = g_deg[i];
    int s = atomicAdd(&g_total, d);
    g_rowstart[i] = s;
    g_pos[i] = s;
}

// ---- bucket edge sources by dst ----
__global__ void k_fill(const int* __restrict__ src, const int* __restrict__ dst) {
    int e = blockIdx.x * blockDim.x + threadIdx.x;
    if (e >= N_EDGES) return;
    int p = atomicAdd(&g_pos[dst[e]], 1);
    g_srcs[p] = src[e];
}

// ---- layer-1 gather (8 lanes/node) fused with hs feature computation ----
__global__ void k_agg1hs(const float* __restrict__ W1, const float* __restrict__ b1) {
    int node = blockIdx.x * 32 + (threadIdx.x >> 3);
    int lane = threadIdx.x & 7;
    int s0 = g_rowstart[node];
    int e0 = s0 + g_deg[node];
    float ax = 0.f, ay = 0.f;
    int j = s0 + lane;
    int sprev = (j < e0) ? g_srcs[j] : 0;
    for (; j < e0; j += 8) {
        int scur = sprev;
        if (j + 8 < e0) sprev = g_srcs[j + 8];
        float2 ab = g_ab[scur];
        ax += ab.x; ay += ab.y;
    }
    // butterfly reduce within the 8-lane group
    #pragma unroll
    for (int m = 4; m >= 1; m >>= 1) {
        ax += __shfl_xor_sync(0xFFFFFFFFu, ax, m);
        ay += __shfl_xor_sync(0xFFFFFFFFu, ay, m);
    }
    float d = g_dinv[node];
    float2 ab = g_ab[node];
    float S0 = d * (ax + ab.x);
    float S1 = d * (ay + ab.y);
    // each lane computes 8 features
    int f0 = lane * 8;
    float4 h4a, h4b;
    float* ha = &h4a.x;
    float* hb = &h4b.x;
    #pragma unroll
    for (int i = 0; i < 4; i++) {
        int f = f0 + i;
        ha[i] = fmaxf(fmaf(S0, W1[f], fmaf(S1, W1[64 + f], b1[f])), 0.f) * d;
    }
    #pragma unroll
    for (int i = 0; i < 4; i++) {
        int f = f0 + 4 + i;
        hb[i] = fmaxf(fmaf(S0, W1[f], fmaf(S1, W1[64 + f], b1[f])), 0.f) * d;
    }
    g_hs[node * 16 + lane * 2]     = h4a;
    g_hs[node * 16 + lane * 2 + 1] = h4b;
}

// ---- layer-2 gather (16 lanes/node) fused with final GEMM + relu + round ----
__global__ void __launch_bounds__(1024) k_agg2out(float* __restrict__ out) {
    __shared__ __align__(16) float wsh[64 * 64];
    __shared__ float vsh[64 * 65];
    __shared__ float bcs[64];
    int tid = threadIdx.x;
    int nb = blockIdx.x * 64;

    // stage weights (overlaps with gather latency)
    #pragma unroll
    for (int t = 0; t < 4; t++) wsh[tid + t * 1024] = g_Wc[tid + t * 1024];
    if (tid < 64) bcs[tid] = g_bc[tid];

    // phase 1: gather + normalize, write v tile to shared
    {
        int nl = tid >> 4;            // node within tile, 0..63
        int lane = tid & 15;          // float4 slice, 0..15
        int node = nb + nl;
        int s0 = g_rowstart[node];
        int e0 = s0 + g_deg[node];
        float4 acc = make_float4(0.f, 0.f, 0.f, 0.f);
        int j = s0;
        int sprev = (j < e0) ? g_srcs[j] : 0;
        for (; j < e0; j++) {
            int scur = sprev;
            if (j + 1 < e0) sprev = g_srcs[j + 1];
            float4 h = g_hs[scur * 16 + lane];
            acc.x += h.x; acc.y += h.y; acc.z += h.z; acc.w += h.w;
        }
        float d = g_dinv[node];
        float4 self = g_hs[node * 16 + lane];
        float* vr = &vsh[nl * 65 + lane * 4];
        vr[0] = d * (acc.x + self.x);
        vr[1] = d * (acc.y + self.y);
        vr[2] = d * (acc.z + self.z);
        vr[3] = d * (acc.w + self.w);
    }
    __syncthreads();

    // phase 2: [64x64] @ [64x64] GEMM, 4 outputs per thread
    int tx = tid & 15;       // output col group (tx*4 .. tx*4+3)
    int row = tid >> 4;      // node row 0..63
    float a0 = 0.f, a1 = 0.f, a2 = 0.f, a3 = 0.f;
    #pragma unroll
    for (int k = 0; k < 64; k++) {
        float4 b = *(const float4*)&wsh[k * 64 + tx * 4];
        float a = vsh[row * 65 + k];
        a0 = fmaf(a, b.x, a0);
        a1 = fmaf(a, b.y, a1);
        a2 = fmaf(a, b.z, a2);
        a3 = fmaf(a, b.w, a3);
    }
    float4 o;
    o.x = rintf(fmaxf(a0 + bcs[tx * 4 + 0], 0.f));
    o.y = rintf(fmaxf(a1 + bcs[tx * 4 + 1], 0.f));
    o.z = rintf(fmaxf(a2 + bcs[tx * 4 + 2], 0.f));
    o.w = rintf(fmaxf(a3 + bcs[tx * 4 + 3], 0.f));
    *(float4*)&out[(nb + row) * 64 + tx * 4] = o;
}

extern "C" void kernel_launch(void* const* d_in, const int* in_sizes, int n_in,
                              void* d_out, int out_size) {
    const float* x   = (const float*)d_in[0];
    const int*   ei  = (const int*)d_in[1];
    const float* W1  = (const float*)d_in[2];
    const float* b1  = (const float*)d_in[3];
    const float* W2  = (const float*)d_in[4];
    const float* b2  = (const float*)d_in[5];
    const float* Wfc = (const float*)d_in[6];
    const float* bfc = (const float*)d_in[7];
    float* out = (float*)d_out;
    const int* src = ei;
    const int* dst = ei + N_EDGES;

    k_zero   <<<(N_NODES + 255) / 256, 256>>>();
    k_prep   <<<16, 256>>>(W2, b2, Wfc, bfc);
    k_deg    <<<(N_EDGES + 255) / 256, 256>>>(dst);
    k_node1  <<<(N_NODES + 255) / 256, 256>>>(x);
    k_alloc  <<<(N_NODES + 255) / 256, 256>>>();
    k_fill   <<<(N_EDGES + 255) / 256, 256>>>(src, dst);
    k_agg1hs <<<N_NODES / 32, 256>>>(W1, b1);
    k_agg2out<<<N_VAR / 64, 1024>>>(out);
}

// round 4
// speedup vs baseline: 1.6410x; 1.0191x over previous
#include <cuda_runtime.h>

#define N_NODES 200000
#define N_VAR   112000
#define N_EDGES 3200000

// ---- device scratch (static, no allocation) ----
__device__ int    g_deg[N_NODES];
__device__ int    g_rowstart[N_NODES];
__device__ int    g_pos[N_NODES];
__device__ int    g_srcs[N_EDGES];
__device__ float  g_dinv[N_NODES];
__device__ float2 g_ab[N_NODES];        // self (a,b) = dinv*(x0,x1)
__device__ float4 g_hs[N_NODES * 16];   // hs = relu(conv1) * dinv, 64 floats/node
__device__ float  g_Wc[64 * 64];        // W2 @ Wfc
__device__ float  g_bc[64];             // b2 @ Wfc + bfc
__device__ int    g_total;

// ---- zero degree counters ----
__global__ void k_zero() {
    int i = blockIdx.x * blockDim.x + threadIdx.x;
    if (i < N_NODES) g_deg[i] = 0;
    if (i == 0) g_total = 0;
}

// ---- precompute Wc = W2 @ Wfc, bc = b2 @ Wfc + bfc ----
__global__ void k_prep(const float* __restrict__ W2, const float* __restrict__ b2,
                       const float* __restrict__ Wfc, const float* __restrict__ bfc) {
    int id = blockIdx.x * 256 + threadIdx.x;   // 0..4095
    int i = id >> 6, j = id & 63;
    float s = 0.f;
    #pragma unroll 8
    for (int k = 0; k < 64; k++) s = fmaf(W2[i * 64 + k], Wfc[k * 64 + j], s);
    g_Wc[id] = s;
    if (id < 64) {
        float sb = bfc[id];
        #pragma unroll 8
        for (int k = 0; k < 64; k++) sb = fmaf(b2[k], Wfc[k * 64 + id], sb);
        g_bc[id] = sb;
    }
}

// ---- in-degree over dst (2 edges/thread) ----
__global__ void k_deg(const int2* __restrict__ dst2) {
    int t = blockIdx.x * blockDim.x + threadIdx.x;
    if (t >= N_EDGES / 2) return;
    int2 d = dst2[t];
    atomicAdd(&g_deg[d.x], 1);
    atomicAdd(&g_deg[d.y], 1);
}

// ---- per-node: dinv, self (a,b), and CSR range via block-local scan ----
__global__ void k_node1(const float* __restrict__ x) {
    int i = blockIdx.x * 256 + threadIdx.x;
    int lane = threadIdx.x & 31, w = threadIdx.x >> 5;
    int d = (i < N_NODES) ? g_deg[i] : 0;

    if (i < N_NODES) {
        float di = rsqrtf((float)d + 1.0f);
        g_dinv[i] = di;
        g_ab[i] = make_float2(di * x[2 * i], di * x[2 * i + 1]);
    }

    // inclusive warp scan of d
    int v = d;
    #pragma unroll
    for (int o = 1; o < 32; o <<= 1) {
        int t = __shfl_up_sync(0xFFFFFFFFu, v, o);
        if (lane >= o) v += t;
    }
    __shared__ int wsum[8];
    __shared__ int base;
    if (lane == 31) wsum[w] = v;
    __syncthreads();
    if (threadIdx.x == 0) {
        int s = 0;
        #pragma unroll
        for (int k = 0; k < 8; k++) { int t = wsum[k]; wsum[k] = s; s += t; }
        base = atomicAdd(&g_total, s);    // 782 single-address atomics total
    }
    __syncthreads();
    if (i < N_NODES) {
        int start = base + wsum[w] + v - d;   // exclusive prefix
        g_rowstart[i] = start;
        g_pos[i] = start;
    }
}

// ---- bucket edge sources by dst ----
__global__ void k_fill(const int* __restrict__ src, const int* __restrict__ dst) {
    int e = blockIdx.x * blockDim.x + threadIdx.x;
    if (e >= N_EDGES) return;
    int p = atomicAdd(&g_pos[dst[e]], 1);
    g_srcs[p] = src[e];
}

// ---- layer-1 gather (8 lanes/node) fused with hs feature computation ----
__global__ void k_agg1hs(const float* __restrict__ W1, const float* __restrict__ b1) {
    int node = blockIdx.x * 32 + (threadIdx.x >> 3);
    int lane = threadIdx.x & 7;
    int s0 = g_rowstart[node];
    int e0 = s0 + g_deg[node];
    float ax = 0.f, ay = 0.f;
    int j = s0 + lane;
    int sprev = (j < e0) ? g_srcs[j] : 0;
    for (; j < e0; j += 8) {
        int scur = sprev;
        if (j + 8 < e0) sprev = g_srcs[j + 8];
        float2 ab = g_ab[scur];
        ax += ab.x; ay += ab.y;
    }
    #pragma unroll
    for (int m = 4; m >= 1; m >>= 1) {
        ax += __shfl_xor_sync(0xFFFFFFFFu, ax, m);
        ay += __shfl_xor_sync(0xFFFFFFFFu, ay, m);
    }
    float d = g_dinv[node];
    float2 ab = g_ab[node];
    float S0 = d * (ax + ab.x);
    float S1 = d * (ay + ab.y);
    int f0 = lane * 8;
    float4 h4a, h4b;
    float* ha = &h4a.x;
    float* hb = &h4b.x;
    #pragma unroll
    for (int i = 0; i < 4; i++) {
        int f = f0 + i;
        ha[i] = fmaxf(fmaf(S0, W1[f], fmaf(S1, W1[64 + f], b1[f])), 0.f) * d;
    }
    #pragma unroll
    for (int i = 0; i < 4; i++) {
        int f = f0 + 4 + i;
        hb[i] = fmaxf(fmaf(S0, W1[f], fmaf(S1, W1[64 + f], b1[f])), 0.f) * d;
    }
    g_hs[node * 16 + lane * 2]     = h4a;
    g_hs[node * 16 + lane * 2 + 1] = h4b;
}

// ---- layer-2 gather (16 lanes/node) fused with final GEMM + relu + round ----
__global__ void __launch_bounds__(1024) k_agg2out(float* __restrict__ out) {
    __shared__ __align__(16) float wsh[64 * 64];
    __shared__ float vsh[64 * 65];
    __shared__ float bcs[64];
    int tid = threadIdx.x;
    int nb = blockIdx.x * 64;

    #pragma unroll
    for (int t = 0; t < 4; t++) wsh[tid + t * 1024] = g_Wc[tid + t * 1024];
    if (tid < 64) bcs[tid] = g_bc[tid];

    {
        int nl = tid >> 4;
        int lane = tid & 15;
        int node = nb + nl;
        int s0 = g_rowstart[node];
        int e0 = s0 + g_deg[node];
        float4 acc = make_float4(0.f, 0.f, 0.f, 0.f);
        int j = s0;
        int sprev = (j < e0) ? g_srcs[j] : 0;
        for (; j < e0; j++) {
            int scur = sprev;
            if (j + 1 < e0) sprev = g_srcs[j + 1];
            float4 h = g_hs[scur * 16 + lane];
            acc.x += h.x; acc.y += h.y; acc.z += h.z; acc.w += h.w;
        }
        float d = g_dinv[node];
        float4 self = g_hs[node * 16 + lane];
        float* vr = &vsh[nl * 65 + lane * 4];
        vr[0] = d * (acc.x + self.x);
        vr[1] = d * (acc.y + self.y);
        vr[2] = d * (acc.z + self.z);
        vr[3] = d * (acc.w + self.w);
    }
    __syncthreads();

    int tx = tid & 15;
    int row = tid >> 4;
    float a0 = 0.f, a1 = 0.f, a2 = 0.f, a3 = 0.f;
    #pragma unroll
    for (int k = 0; k < 64; k++) {
        float4 b = *(const float4*)&wsh[k * 64 + tx * 4];
        float a = vsh[row * 65 + k];
        a0 = fmaf(a, b.x, a0);
        a1 = fmaf(a, b.y, a1);
        a2 = fmaf(a, b.z, a2);
        a3 = fmaf(a, b.w, a3);
    }
    float4 o;
    o.x = rintf(fmaxf(a0 + bcs[tx * 4 + 0], 0.f));
    o.y = rintf(fmaxf(a1 + bcs[tx * 4 + 1], 0.f));
    o.z = rintf(fmaxf(a2 + bcs[tx * 4 + 2], 0.f));
    o.w = rintf(fmaxf(a3 + bcs[tx * 4 + 3], 0.f));
    *(float4*)&out[(nb + row) * 64 + tx * 4] = o;
}

extern "C" void kernel_launch(void* const* d_in, const int* in_sizes, int n_in,
                              void* d_out, int out_size) {
    const float* x   = (const float*)d_in[0];
    const int*   ei  = (const int*)d_in[1];
    const float* W1  = (const float*)d_in[2];
    const float* b1  = (const float*)d_in[3];
    const float* W2  = (const float*)d_in[4];
    const float* b2  = (const float*)d_in[5];
    const float* Wfc = (const float*)d_in[6];
    const float* bfc = (const float*)d_in[7];
    float* out = (float*)d_out;
    const int* src = ei;
    const int* dst = ei + N_EDGES;

    k_zero   <<<(N_NODES + 255) / 256, 256>>>();
    k_prep   <<<16, 256>>>(W2, b2, Wfc, bfc);
    k_deg    <<<(N_EDGES / 2 + 255) / 256, 256>>>((const int2*)dst);
    k_node1  <<<(N_NODES + 255) / 256, 256>>>(x);
    k_fill   <<<(N_EDGES + 255) / 256, 256>>>(src, dst);
    k_agg1hs <<<N_NODES / 32, 256>>>(W1, b1);
    k_agg2out<<<N_VAR / 64, 1024>>>(out);
}

// round 5
// speedup vs baseline: 1.6751x; 1.0208x over previous
#include <cuda_runtime.h>

#define N_NODES 200000
#define N_VAR   112000
#define N_EDGES 3200000

// ---- device scratch (static, no allocation) ----
__device__ int    g_deg[N_NODES];
__device__ int    g_rowstart[N_NODES];
__device__ int    g_pos[N_VAR];
__device__ int    g_srcs[N_EDGES];      // only first ~1.79M (var-dst edges) used
__device__ float  g_dinv[N_NODES];
__device__ float2 g_ab[N_NODES];        // self (a,b) = dinv*(x0,x1)
__device__ float2 g_AB[N_NODES];        // layer-1 scatter accumulators
__device__ float4 g_hs[N_NODES * 16];   // hs = relu(conv1) * dinv, 64 floats/node
__device__ float  g_Wc[64 * 64];        // W2 @ Wfc
__device__ float  g_bc[64];             // b2 @ Wfc + bfc
__device__ int    g_total;

// ---- zero accumulators ----
__global__ void k_zero() {
    int i = blockIdx.x * blockDim.x + threadIdx.x;
    if (i < N_NODES) { g_deg[i] = 0; g_AB[i] = make_float2(0.f, 0.f); }
    if (i == 0) g_total = 0;
}

// ---- precompute Wc = W2 @ Wfc, bc = b2 @ Wfc + bfc ----
__global__ void k_prep(const float* __restrict__ W2, const float* __restrict__ b2,
                       const float* __restrict__ Wfc, const float* __restrict__ bfc) {
    int id = blockIdx.x * 256 + threadIdx.x;   // 0..4095
    int i = id >> 6, j = id & 63;
    float s = 0.f;
    #pragma unroll 8
    for (int k = 0; k < 64; k++) s = fmaf(W2[i * 64 + k], Wfc[k * 64 + j], s);
    g_Wc[id] = s;
    if (id < 64) {
        float sb = bfc[id];
        #pragma unroll 8
        for (int k = 0; k < 64; k++) sb = fmaf(b2[k], Wfc[k * 64 + id], sb);
        g_bc[id] = sb;
    }
}

// ---- in-degree over dst (4 edges/thread) ----
__global__ void k_deg(const int4* __restrict__ dst4) {
    int t = blockIdx.x * blockDim.x + threadIdx.x;
    if (t >= N_EDGES / 4) return;
    int4 d = dst4[t];
    atomicAdd(&g_deg[d.x], 1);
    atomicAdd(&g_deg[d.y], 1);
    atomicAdd(&g_deg[d.z], 1);
    atomicAdd(&g_deg[d.w], 1);
}

// ---- per-node: dinv, self (a,b); CSR ranges for VAR nodes via block scan ----
__global__ void k_node1(const float* __restrict__ x) {
    int i = blockIdx.x * 256 + threadIdx.x;
    int lane = threadIdx.x & 31, w = threadIdx.x >> 5;
    int d = (i < N_NODES) ? g_deg[i] : 0;

    if (i < N_NODES) {
        float di = rsqrtf((float)d + 1.0f);
        g_dinv[i] = di;
        g_ab[i] = make_float2(di * x[2 * i], di * x[2 * i + 1]);
    }

    int vd = (i < N_VAR) ? d : 0;      // only var nodes get CSR space
    int v = vd;
    #pragma unroll
    for (int o = 1; o < 32; o <<= 1) {
        int t = __shfl_up_sync(0xFFFFFFFFu, v, o);
        if (lane >= o) v += t;
    }
    __shared__ int wsum[8];
    __shared__ int base;
    if (lane == 31) wsum[w] = v;
    __syncthreads();
    if (threadIdx.x == 0) {
        int s = 0;
        #pragma unroll
        for (int k = 0; k < 8; k++) { int t = wsum[k]; wsum[k] = s; s += t; }
        base = atomicAdd(&g_total, s);
    }
    __syncthreads();
    if (i < N_NODES) {
        int start = base + wsum[w] + v - vd;   // exclusive prefix
        g_rowstart[i] = start;
        if (i < N_VAR) g_pos[i] = start;
    }
}

// ---- per edge: layer-1 scalar scatter + var-dst CSR bucketing (2 edges/thread) ----
__global__ void k_fill(const int2* __restrict__ src2, const int2* __restrict__ dst2) {
    int t = blockIdx.x * blockDim.x + threadIdx.x;
    if (t >= N_EDGES / 2) return;
    int2 s = src2[t], d = dst2[t];

    float2 a = g_ab[s.x];
    asm volatile("red.global.add.v2.f32 [%0], {%1, %2};"
                 :: "l"(&g_AB[d.x]), "f"(a.x), "f"(a.y) : "memory");
    if (d.x < N_VAR) { int p = atomicAdd(&g_pos[d.x], 1); g_srcs[p] = s.x; }

    float2 b = g_ab[s.y];
    asm volatile("red.global.add.v2.f32 [%0], {%1, %2};"
                 :: "l"(&g_AB[d.y]), "f"(b.x), "f"(b.y) : "memory");
    if (d.y < N_VAR) { int p = atomicAdd(&g_pos[d.y], 1); g_srcs[p] = s.y; }
}

// ---- per (node, 4 features): hs = relu(conv1)*dinv (pure elementwise) ----
__global__ void k_hs(const float* __restrict__ W1, const float* __restrict__ b1) {
    int tid = blockIdx.x * blockDim.x + threadIdx.x;
    if (tid >= N_NODES * 16) return;
    int i = tid >> 4, q = tid & 15;
    float d = g_dinv[i];
    float2 AB = g_AB[i];
    float2 ab = g_ab[i];
    float S0 = d * (AB.x + ab.x);
    float S1 = d * (AB.y + ab.y);
    float4 h;
    float* hp = &h.x;
    #pragma unroll
    for (int j = 0; j < 4; j++) {
        int f = q * 4 + j;
        hp[j] = fmaxf(fmaf(S0, W1[f], fmaf(S1, W1[64 + f], b1[f])), 0.f) * d;
    }
    g_hs[tid] = h;
}

// ---- layer-2: balanced edge-parallel gather + fused GEMM + relu + round ----
__global__ void __launch_bounds__(1024) k_agg2out(float* __restrict__ out) {
    __shared__ __align__(16) float wsh[64 * 64];
    __shared__ float vsh[64 * 65];
    __shared__ float bcs[64];
    __shared__ int   rs[65];
    int tid = threadIdx.x;
    int nb = blockIdx.x * 64;

    #pragma unroll
    for (int t = 0; t < 4; t++) { wsh[tid + t * 1024] = g_Wc[tid + t * 1024]; vsh[tid + t * 1024] = 0.f; }
    if (tid < 64) { vsh[4096 + tid] = 0.f; bcs[tid] = g_bc[tid]; rs[tid] = g_rowstart[nb + tid]; }
    if (tid == 63) rs[64] = g_rowstart[nb + 63] + g_deg[nb + 63];
    __syncthreads();

    // phase 1: tile's edges are contiguous [rs[0], rs[64]); split evenly across 32 warps
    {
        int e0 = rs[0], e1 = rs[64];
        int warp = tid >> 5, lane = tid & 31;
        int chunk = ((e1 - e0) + 31) >> 5;
        int wb = e0 + warp * chunk;
        int we = min(wb + chunk, e1);
        if (wb < we) {
            // first node whose range contains wb: smallest n with rs[n+1] > wb
            int lo = 0, hi = 63;
            while (lo < hi) { int mid = (lo + hi) >> 1; if (rs[mid + 1] <= wb) lo = mid + 1; else hi = mid; }
            int n = lo;
            int e = wb;
            while (e < we) {
                int nend = min(rs[n + 1], we);
                float ax = 0.f, ay = 0.f;
                for (; e < nend; e++) {
                    int s = g_srcs[e];
                    float2 h = ((const float2*)g_hs)[s * 32 + lane];
                    ax += h.x; ay += h.y;
                }
                atomicAdd(&vsh[n * 65 + lane * 2], ax);
                atomicAdd(&vsh[n * 65 + lane * 2 + 1], ay);
                n++;
            }
        }
    }
    __syncthreads();

    // phase 1.5: add self term, normalize
    #pragma unroll
    for (int t = 0; t < 4; t++) {
        int id = tid + t * 1024;
        int r = id >> 6, k = id & 63;
        int node = nb + r;
        float d = g_dinv[node];
        float self = ((const float*)g_hs)[node * 64 + k];
        vsh[r * 65 + k] = d * (vsh[r * 65 + k] + self);
    }
    __syncthreads();

    // phase 2: [64x64] @ [64x64] GEMM, 4 outputs per thread
    int tx = tid & 15;
    int row = tid >> 4;
    float a0 = 0.f, a1 = 0.f, a2 = 0.f, a3 = 0.f;
    #pragma unroll
    for (int k = 0; k < 64; k++) {
        float4 b = *(const float4*)&wsh[k * 64 + tx * 4];
        float a = vsh[row * 65 + k];
        a0 = fmaf(a, b.x, a0);
        a1 = fmaf(a, b.y, a1);
        a2 = fmaf(a, b.z, a2);
        a3 = fmaf(a, b.w, a3);
    }
    float4 o;
    o.x = rintf(fmaxf(a0 + bcs[tx * 4 + 0], 0.f));
    o.y = rintf(fmaxf(a1 + bcs[tx * 4 + 1], 0.f));
    o.z = rintf(fmaxf(a2 + bcs[tx * 4 + 2], 0.f));
    o.w = rintf(fmaxf(a3 + bcs[tx * 4 + 3], 0.f));
    *(float4*)&out[(nb + row) * 64 + tx * 4] = o;
}

extern "C" void kernel_launch(void* const* d_in, const int* in_sizes, int n_in,
                              void* d_out, int out_size) {
    const float* x   = (const float*)d_in[0];
    const int*   ei  = (const int*)d_in[1];
    const float* W1  = (const float*)d_in[2];
    const float* b1  = (const float*)d_in[3];
    const float* W2  = (const float*)d_in[4];
    const float* b2  = (const float*)d_in[5];
    const float* Wfc = (const float*)d_in[6];
    const float* bfc = (const float*)d_in[7];
    float* out = (float*)d_out;
    const int* src = ei;
    const int* dst = ei + N_EDGES;

    k_zero   <<<(N_NODES + 255) / 256, 256>>>();
    k_prep   <<<16, 256>>>(W2, b2, Wfc, bfc);
    k_deg    <<<(N_EDGES / 4 + 255) / 256, 256>>>((const int4*)dst);
    k_node1  <<<(N_NODES + 255) / 256, 256>>>(x);
    k_fill   <<<(N_EDGES / 2 + 255) / 256, 256>>>((const int2*)src, (const int2*)dst);
    k_hs     <<<(N_NODES * 16 + 255) / 256, 256>>>(W1, b1);
    k_agg2out<<<N_VAR / 64, 1024>>>(out);
}